// round 15
// baseline (speedup 1.0000x reference)
#include <cuda_runtime.h>
#include <cstdint>

#define HW 65536
#define IMGW 256
#define CH 384

// hidden activations, channel-last: [b][pix][384]  (402.7 MB)
__device__ float g_hidden[(size_t)4 * HW * CH];
__device__ float g_wdw_t[9 * 384];       // [tap][channel]
__device__ float2 g_wout_p[64 * 64];     // [c2][o] = (wout[o][2c2], wout[o][2c2+1])

typedef unsigned long long u64;
typedef unsigned int u32;

__device__ __forceinline__ u64 pack2(float lo, float hi) {
    u64 r; asm("mov.b64 %0, {%1, %2};" : "=l"(r) : "f"(lo), "f"(hi)); return r;
}
__device__ __forceinline__ void ffma2(u64 &d, u64 a, u64 b) {
    asm("fma.rn.f32x2 %0, %1, %2, %0;" : "+l"(d) : "l"(a), "l"(b));
}
__device__ __forceinline__ void unpack2(float &lo, float &hi, u64 v) {
    asm("mov.b64 {%0, %1}, %2;" : "=f"(lo), "=f"(hi) : "l"(v));
}
__device__ __forceinline__ u32 cvt_tf32(float f) {
    u32 r; asm("cvt.rna.tf32.f32 %0, %1;" : "=r"(r) : "f"(f)); return r;
}
__device__ __forceinline__ void mma_tf32(float* d, const u32* a, u32 b0, u32 b1) {
    asm volatile("mma.sync.aligned.m16n8k8.row.col.f32.tf32.tf32.f32 "
                 "{%0,%1,%2,%3}, {%4,%5,%6,%7}, {%8,%9}, {%0,%1,%2,%3};"
                 : "+f"(d[0]), "+f"(d[1]), "+f"(d[2]), "+f"(d[3])
                 : "r"(a[0]), "r"(a[1]), "r"(a[2]), "r"(a[3]), "r"(b0), "r"(b1));
}

// ---------------------------------------------------------------------------
// K1: 1x1 conv 64->384 via mma.sync m16n8k8 TF32.
//   grid (512, 3, 4), block 256 (8 warps). Tile: 128 o x 128 pix, K=64.
//   Warp w computes o-rows [w*16, w*16+16) x all 128 pixels.
//   smem: Xs [128 pix][68] (tf32 bits) = 34816 B; reused as epilogue stage.
//   A (weights) lives in 32 regs/thread, loaded from global (L2-hot).
//   Block (0,0,0) additionally preps g_wdw_t / g_wout_p for K2.
// ---------------------------------------------------------------------------
__global__ __launch_bounds__(256) void k1_conv1x1(const float* __restrict__ x,
                                                  const float* __restrict__ wh,
                                                  const float* __restrict__ wdw,
                                                  const float* __restrict__ wout) {
    extern __shared__ float sm[];
    u32* XsU = (u32*)sm;          // [128][68]
    const int b  = blockIdx.z;
    const int ob = blockIdx.y;
    const int pb = blockIdx.x;
    const int tid  = threadIdx.x;
    const int lane = tid & 31;
    const int w    = tid >> 5;

    if (pb == 0 && ob == 0 && b == 0) {
        for (int i = tid; i < 9 * 384; i += 256) {
            int o = i / 9, k = i % 9;
            g_wdw_t[k * 384 + o] = wdw[i];
        }
        for (int i = tid; i < 64 * 64; i += 256) {
            int c2 = i >> 6, o = i & 63;
            g_wout_p[c2 * 64 + o] = make_float2(wout[o * 128 + 2 * c2],
                                                wout[o * 128 + 2 * c2 + 1]);
        }
    }

    // ---- fill Xs transposed: Xs[pix][c], tf32-rounded ----
    {
        const int p = tid & 127, hf = tid >> 7;    // hf selects c-half
        const float* xp = x + ((size_t)b * 64 + hf * 32) * HW + (size_t)pb * 128 + p;
        #pragma unroll 8
        for (int c = 0; c < 32; c++) {
            XsU[p * 68 + hf * 32 + c] = cvt_tf32(xp[(size_t)c * HW]);
        }
    }

    // ---- A fragments: 8 k-steps x 4 regs ----
    const int o0 = w * 16;
    const int r  = lane >> 2;
    const int kc = lane & 3;
    u32 a[8][4];
    {
        const float* wr0 = wh + (size_t)(ob * 128 + o0 + r) * 64;
        const float* wr8 = wh + (size_t)(ob * 128 + o0 + r + 8) * 64;
        #pragma unroll
        for (int kk = 0; kk < 8; kk++) {
            a[kk][0] = cvt_tf32(__ldg(wr0 + kk * 8 + kc));
            a[kk][1] = cvt_tf32(__ldg(wr8 + kk * 8 + kc));
            a[kk][2] = cvt_tf32(__ldg(wr0 + kk * 8 + kc + 4));
            a[kk][3] = cvt_tf32(__ldg(wr8 + kk * 8 + kc + 4));
        }
    }
    __syncthreads();

    // ---- mma mainloop: 8 k-steps x 16 pixel-tiles ----
    float acc[16][4];
    #pragma unroll
    for (int n = 0; n < 16; n++)
        #pragma unroll
        for (int c = 0; c < 4; c++) acc[n][c] = 0.f;

    {
        const u32* Xb = XsU + (lane >> 2) * 68 + (lane & 3);
        #pragma unroll
        for (int kk = 0; kk < 8; kk++) {
            #pragma unroll
            for (int n = 0; n < 16; n++) {
                u32 b0 = Xb[n * 8 * 68 + kk * 8];
                u32 b1 = Xb[n * 8 * 68 + kk * 8 + 4];
                mma_tf32(acc[n], a[kk], b0, b1);
            }
        }
    }
    __syncthreads();

    // ---- epilogue: two 64-pixel halves staged through smem [64][132] ----
    #pragma unroll
    for (int half = 0; half < 2; half++) {
        #pragma unroll
        for (int nl = 0; nl < 8; nl++) {
            int n = half * 8 + nl;
            #pragma unroll
            for (int c = 0; c < 4; c++) {
                int pixl = nl * 8 + 2 * (lane & 3) + (c & 1);
                int oo = o0 + (lane >> 2) + 8 * (c >> 1);
                sm[pixl * 132 + oo] = acc[n][c];
            }
        }
        __syncthreads();
        {
            const int col4 = tid & 31, prow = tid >> 5;
            #pragma unroll
            for (int ii = 0; ii < 8; ii++) {
                int pix = prow + 8 * ii;
                float4 v = *(float4*)&sm[pix * 132 + col4 * 4];
                *(float4*)&g_hidden[((size_t)b * HW + (size_t)pb * 128 + half * 64 + pix) * CH
                                    + ob * 128 + col4 * 4] = v;
            }
        }
        __syncthreads();
    }
}

// ---------------------------------------------------------------------------
// K2: per-patch dwconv + 8x8 circular conv + LN + gate + 1x1 conv out.
//   (unchanged from R12: 3 CTAs/SM, fused phase-5 gate; measured 349 us)
// ---------------------------------------------------------------------------
__device__ __forceinline__ void loadrow10(float* r, const float* hid, int y, int x0, int c) {
    if ((unsigned)y < 256u) {
        #pragma unroll
        for (int j = 0; j < 10; j++) {
            int xx = x0 - 1 + j;
            r[j] = ((unsigned)xx < 256u) ? hid[((size_t)y * IMGW + xx) * CH + c] : 0.f;
        }
    } else {
        #pragma unroll
        for (int j = 0; j < 10; j++) r[j] = 0.f;
    }
}

__device__ __forceinline__ void dwconv_half(const float* hid, int c, int y0, int x0,
                                            int oy0, float* sdst) {
    float w9[9];
    #pragma unroll
    for (int k = 0; k < 9; k++) w9[k] = g_wdw_t[k * 384 + c];
    float r0[10], r1[10], r2[10];
    loadrow10(r0, hid, y0 + oy0 - 1, x0, c);
    loadrow10(r1, hid, y0 + oy0,     x0, c);
    #pragma unroll
    for (int oy = 0; oy < 4; oy++) {
        loadrow10(r2, hid, y0 + oy0 + oy + 1, x0, c);
        #pragma unroll
        for (int ox = 0; ox < 8; ox++) {
            float s = r0[ox] * w9[0] + r0[ox + 1] * w9[1] + r0[ox + 2] * w9[2]
                    + r1[ox] * w9[3] + r1[ox + 1] * w9[4] + r1[ox + 2] * w9[5]
                    + r2[ox] * w9[6] + r2[ox + 1] * w9[7] + r2[ox + 2] * w9[8];
            sdst[((oy0 + oy) * 8 + ox) * 128] = s;
        }
        #pragma unroll
        for (int j = 0; j < 10; j++) { r0[j] = r1[j]; r1[j] = r2[j]; }
    }
}

__global__ __launch_bounds__(256, 3) void k2_patch(const float* __restrict__ nw_g,
                                                   const float* __restrict__ nb_g,
                                                   float* __restrict__ out) {
    extern __shared__ float sm2[];
    float* sq  = sm2;
    float* sk  = sm2 + 8192;
    float* sA  = sm2 + 16384;
    float* sB  = sm2 + 16640;
    float* smu = sm2 + 16896;
    float* srs = sm2 + 16960;

    const int b = blockIdx.z, py = blockIdx.y, px = blockIdx.x;
    const int t = threadIdx.x;
    const int ch = t & 127, h = t >> 7;
    const int oy0 = 4 * h;
    const float* hid = g_hidden + (size_t)b * HW * CH;
    const int y0 = py * 8, x0 = px * 8;

    dwconv_half(hid, ch,       y0, x0, oy0, sq + ch);
    dwconv_half(hid, 128 + ch, y0, x0, oy0, sk + ch);
    __syncthreads();

    float acc[32];
    #pragma unroll
    for (int i = 0; i < 32; i++) acc[i] = 0.f;
    {
        const float* sqc = sq + ch;
        const float* skc = sk + ch;
        #pragma unroll
        for (int a = 0; a < 8; a++) {
            float qr[8];
            #pragma unroll
            for (int bb = 0; bb < 8; bb++) qr[bb] = sqc[(a * 8 + bb) * 128];
            #pragma unroll
            for (int i = 0; i < 4; i++) {
                const int u = (oy0 + i - a) & 7;
                float kr[8];
                #pragma unroll
                for (int v = 0; v < 8; v++) kr[v] = skc[(u * 8 + v) * 128];
                #pragma unroll
                for (int bb = 0; bb < 8; bb++)
                    #pragma unroll
                    for (int v = 0; v < 8; v++)
                        acc[(i << 3) + ((bb + v) & 7)] += qr[bb] * kr[v];
            }
        }
    }
    __syncthreads();

    #pragma unroll
    for (int i = 0; i < 32; i++) sq[(oy0 * 8 + i) * 128 + ch] = acc[i];
    __syncthreads();

    {
        const int p = t & 63, g4 = t >> 6;
        float s = 0.f, s2 = 0.f;
        #pragma unroll 8
        for (int i = 0; i < 32; i++) {
            int c = g4 * 32 + i;
            float v = sq[p * 128 + ((c + p) & 127)];
            s += v; s2 += v * v;
        }
        sA[g4 * 64 + p] = s; sB[g4 * 64 + p] = s2;
    }
    __syncthreads();
    if (t < 64) {
        float s  = sA[t] + sA[t + 64] + sA[t + 128] + sA[t + 192];
        float s2 = sB[t] + sB[t + 64] + sB[t + 128] + sB[t + 192];
        float mu = s * (1.f / 128.f);
        float var = s2 * (1.f / 128.f) - mu * mu;
        smu[t] = mu;
        srs[t] = rsqrtf(var + 1e-5f);
    }
    __syncthreads();

    {
        float w9[9];
        #pragma unroll
        for (int k = 0; k < 9; k++) w9[k] = g_wdw_t[k * 384 + 256 + ch];
        const float nw = nw_g[ch], nb = nb_g[ch];
        float r0[10], r1[10], r2[10];
        loadrow10(r0, hid, y0 + oy0 - 1, x0, 256 + ch);
        loadrow10(r1, hid, y0 + oy0,     x0, 256 + ch);
        #pragma unroll
        for (int oy = 0; oy < 4; oy++) {
            loadrow10(r2, hid, y0 + oy0 + oy + 1, x0, 256 + ch);
            #pragma unroll
            for (int ox = 0; ox < 8; ox++) {
                float v = r0[ox] * w9[0] + r0[ox + 1] * w9[1] + r0[ox + 2] * w9[2]
                        + r1[ox] * w9[3] + r1[ox + 1] * w9[4] + r1[ox + 2] * w9[5]
                        + r2[ox] * w9[6] + r2[ox + 1] * w9[7] + r2[ox + 2] * w9[8];
                int p = (oy0 + oy) * 8 + ox;
                float nrm = (sq[p * 128 + ch] - smu[p]) * srs[p] * nw + nb;
                sk[p * 128 + ch] = v * nrm;
            }
            #pragma unroll
            for (int j = 0; j < 10; j++) { r0[j] = r1[j]; r1[j] = r2[j]; }
        }
    }
    __syncthreads();

    {
        const int o = t & 63, ph = t >> 6, p0 = ph << 4;
        u64 pa[16];
        #pragma unroll
        for (int p = 0; p < 16; p++) pa[p] = 0ULL;
        #pragma unroll 2
        for (int c4 = 0; c4 < 32; c4++) {
            float2 w01 = __ldg(&g_wout_p[(2 * c4) * 64 + o]);
            float2 w23 = __ldg(&g_wout_p[(2 * c4 + 1) * 64 + o]);
            u64 wq01 = pack2(w01.x, w01.y);
            u64 wq23 = pack2(w23.x, w23.y);
            const float* gk = sk + 4 * c4;
            #pragma unroll
            for (int p = 0; p < 16; p++) {
                ulonglong2 g = *(const ulonglong2*)(gk + (p0 + p) * 128);
                ffma2(pa[p], g.x, wq01);
                ffma2(pa[p], g.y, wq23);
            }
        }
        #pragma unroll
        for (int p = 0; p < 16; p++) {
            float lo, hi; unpack2(lo, hi, pa[p]);
            sq[o * 66 + p0 + p] = lo + hi;
        }
    }
    __syncthreads();

    for (int i = t; i < 4096; i += 256) {
        int oo = i >> 6, p = i & 63;
        int y = y0 + (p >> 3), x = x0 + (p & 7);
        out[(((size_t)b * 64 + oo) * IMGW + y) * IMGW + x] = sq[oo * 66 + p];
    }
}

// ---------------------------------------------------------------------------
extern "C" void kernel_launch(void* const* d_in, const int* in_sizes, int n_in,
                              void* d_out, int out_size) {
    const float* x    = (const float*)d_in[0];
    const float* wh   = (const float*)d_in[1];
    const float* wdw  = (const float*)d_in[2];
    const float* nw   = (const float*)d_in[3];
    const float* nb   = (const float*)d_in[4];
    const float* wout = (const float*)d_in[5];
    float* out = (float*)d_out;

    cudaFuncSetAttribute(k1_conv1x1, cudaFuncAttributeMaxDynamicSharedMemorySize, 34816);
    cudaFuncSetAttribute(k2_patch,   cudaFuncAttributeMaxDynamicSharedMemorySize, 68096);

    k1_conv1x1<<<dim3(512, 3, 4), 256, 34816>>>(x, wh, wdw, wout);
    k2_patch<<<dim3(32, 32, 4), 256, 68096>>>(nw, nb, out);
}

// round 17
// speedup vs baseline: 1.5270x; 1.5270x over previous
#include <cuda_runtime.h>
#include <cstdint>

#define HW 65536
#define IMGW 256
#define CH 384

// hidden activations, channel-last: [b][pix][384]  (402.7 MB)
__device__ float g_hidden[(size_t)4 * HW * CH];
__device__ float g_wdw_t[9 * 384];       // [tap][channel]
__device__ float2 g_wout_p[64 * 64];     // [c2][o] = (wout[o][2c2], wout[o][2c2+1])

typedef unsigned long long u64;
typedef unsigned int u32;

__device__ __forceinline__ u64 pack2(float lo, float hi) {
    u64 r; asm("mov.b64 %0, {%1, %2};" : "=l"(r) : "f"(lo), "f"(hi)); return r;
}
__device__ __forceinline__ void ffma2(u64 &d, u64 a, u64 b) {
    asm("fma.rn.f32x2 %0, %1, %2, %0;" : "+l"(d) : "l"(a), "l"(b));
}
__device__ __forceinline__ void unpack2(float &lo, float &hi, u64 v) {
    asm("mov.b64 {%0, %1}, %2;" : "=f"(lo), "=f"(hi) : "l"(v));
}
__device__ __forceinline__ u32 cvt_tf32(float f) {
    u32 r; asm("cvt.rna.tf32.f32 %0, %1;" : "=r"(r) : "f"(f)); return r;
}
__device__ __forceinline__ void mma_tf32(float* d, const u32* a, u32 b0, u32 b1) {
    asm volatile("mma.sync.aligned.m16n8k8.row.col.f32.tf32.tf32.f32 "
                 "{%0,%1,%2,%3}, {%4,%5,%6,%7}, {%8,%9}, {%0,%1,%2,%3};"
                 : "+f"(d[0]), "+f"(d[1]), "+f"(d[2]), "+f"(d[3])
                 : "r"(a[0]), "r"(a[1]), "r"(a[2]), "r"(a[3]), "r"(b0), "r"(b1));
}

// ---------------------------------------------------------------------------
// K1: 1x1 conv 64->384 via mma.sync m16n8k8 TF32.
//   grid (512, 3, 4), block 256 (8 warps). Tile: 128 o x 128 pix, K=64.
//   Warp w computes o-rows [w*16, w*16+16) x all 128 pixels.
//   Xs stored FRAGMENT-MAJOR as float2 k-pairs (j, j+4):
//     unit idx = ((n*8 + kk)*32) + row*4 + ((j&3) ^ (row&3) ^ (n&3))
//   -> mainloop does ONE conflict-free LDS.64 per (kk, n) instead of 2x LDS.32.
//   A (weights) lives in 32 regs/thread, loaded from global (L2-hot).
//   Block (0,0,0) additionally preps g_wdw_t / g_wout_p for K2.
// ---------------------------------------------------------------------------
__global__ __launch_bounds__(256) void k1_conv1x1(const float* __restrict__ x,
                                                  const float* __restrict__ wh,
                                                  const float* __restrict__ wdw,
                                                  const float* __restrict__ wout) {
    extern __shared__ float sm[];
    u32* XsU = (u32*)sm;          // 8192 u32 = 32 KB (pair layout)
    const int b  = blockIdx.z;
    const int ob = blockIdx.y;
    const int pb = blockIdx.x;
    const int tid  = threadIdx.x;
    const int lane = tid & 31;
    const int w    = tid >> 5;

    if (pb == 0 && ob == 0 && b == 0) {
        for (int i = tid; i < 9 * 384; i += 256) {
            int o = i / 9, k = i % 9;
            g_wdw_t[k * 384 + o] = wdw[i];
        }
        for (int i = tid; i < 64 * 64; i += 256) {
            int c2 = i >> 6, o = i & 63;
            g_wout_p[c2 * 64 + o] = make_float2(wout[o * 128 + 2 * c2],
                                                wout[o * 128 + 2 * c2 + 1]);
        }
    }

    // ---- fill Xs (pair layout), tf32-rounded ----
    {
        const int p = tid & 127, hf = tid >> 7;    // hf selects c-half
        const int n = p >> 3, row = p & 7;
        const float* xp = x + ((size_t)b * 64 + hf * 32) * HW + (size_t)pb * 128 + p;
        #pragma unroll 8
        for (int cc = 0; cc < 32; cc++) {
            int c = hf * 32 + cc;
            int kk = c >> 3, j = c & 7, q = j & 3, e = j >> 2;
            int q2 = q ^ (row & 3) ^ (n & 3);
            XsU[(((n * 8 + kk) * 32) + row * 4 + q2) * 2 + e] = cvt_tf32(xp[(size_t)cc * HW]);
        }
    }

    // ---- A fragments: 8 k-steps x 4 regs ----
    const int o0 = w * 16;
    const int r  = lane >> 2;
    const int kc = lane & 3;
    u32 a[8][4];
    {
        const float* wr0 = wh + (size_t)(ob * 128 + o0 + r) * 64;
        const float* wr8 = wh + (size_t)(ob * 128 + o0 + r + 8) * 64;
        #pragma unroll
        for (int kk = 0; kk < 8; kk++) {
            a[kk][0] = cvt_tf32(__ldg(wr0 + kk * 8 + kc));
            a[kk][1] = cvt_tf32(__ldg(wr8 + kk * 8 + kc));
            a[kk][2] = cvt_tf32(__ldg(wr0 + kk * 8 + kc + 4));
            a[kk][3] = cvt_tf32(__ldg(wr8 + kk * 8 + kc + 4));
        }
    }
    __syncthreads();

    // ---- mma mainloop: 8 k-steps x 16 pixel-tiles, 1 LDS.64 per step ----
    float acc[16][4];
    #pragma unroll
    for (int n = 0; n < 16; n++)
        #pragma unroll
        for (int c = 0; c < 4; c++) acc[n][c] = 0.f;

    {
        const int rbase = r * 4;           // row*4
        const int rx = kc ^ (r & 3);       // qc ^ (row&3)
        #pragma unroll
        for (int kk = 0; kk < 8; kk++) {
            #pragma unroll
            for (int n = 0; n < 16; n++) {
                int u = (n * 8 + kk) * 32 + rbase + (rx ^ (n & 3));
                uint2 bb = *(const uint2*)(XsU + u * 2);
                mma_tf32(acc[n], a[kk], bb.x, bb.y);
            }
        }
    }
    __syncthreads();

    // ---- epilogue: two 64-pixel halves staged through smem [64][132] ----
    #pragma unroll
    for (int half = 0; half < 2; half++) {
        #pragma unroll
        for (int nl = 0; nl < 8; nl++) {
            int n = half * 8 + nl;
            #pragma unroll
            for (int c = 0; c < 4; c++) {
                int pixl = nl * 8 + 2 * (lane & 3) + (c & 1);
                int oo = o0 + (lane >> 2) + 8 * (c >> 1);
                sm[pixl * 132 + oo] = acc[n][c];
            }
        }
        __syncthreads();
        {
            const int col4 = tid & 31, prow = tid >> 5;
            #pragma unroll
            for (int ii = 0; ii < 8; ii++) {
                int pix = prow + 8 * ii;
                float4 v = *(float4*)&sm[pix * 132 + col4 * 4];
                *(float4*)&g_hidden[((size_t)b * HW + (size_t)pb * 128 + half * 64 + pix) * CH
                                    + ob * 128 + col4 * 4] = v;
            }
        }
        __syncthreads();
    }
}

// ---------------------------------------------------------------------------
// K2: per-patch dwconv + 8x8 circular conv + LN + gate + 1x1 conv out.
//   (unchanged from R12: 3 CTAs/SM, fused phase-5 gate; 349 us at full clock)
// ---------------------------------------------------------------------------
__device__ __forceinline__ void loadrow10(float* r, const float* hid, int y, int x0, int c) {
    if ((unsigned)y < 256u) {
        #pragma unroll
        for (int j = 0; j < 10; j++) {
            int xx = x0 - 1 + j;
            r[j] = ((unsigned)xx < 256u) ? hid[((size_t)y * IMGW + xx) * CH + c] : 0.f;
        }
    } else {
        #pragma unroll
        for (int j = 0; j < 10; j++) r[j] = 0.f;
    }
}

__device__ __forceinline__ void dwconv_half(const float* hid, int c, int y0, int x0,
                                            int oy0, float* sdst) {
    float w9[9];
    #pragma unroll
    for (int k = 0; k < 9; k++) w9[k] = g_wdw_t[k * 384 + c];
    float r0[10], r1[10], r2[10];
    loadrow10(r0, hid, y0 + oy0 - 1, x0, c);
    loadrow10(r1, hid, y0 + oy0,     x0, c);
    #pragma unroll
    for (int oy = 0; oy < 4; oy++) {
        loadrow10(r2, hid, y0 + oy0 + oy + 1, x0, c);
        #pragma unroll
        for (int ox = 0; ox < 8; ox++) {
            float s = r0[ox] * w9[0] + r0[ox + 1] * w9[1] + r0[ox + 2] * w9[2]
                    + r1[ox] * w9[3] + r1[ox + 1] * w9[4] + r1[ox + 2] * w9[5]
                    + r2[ox] * w9[6] + r2[ox + 1] * w9[7] + r2[ox + 2] * w9[8];
            sdst[((oy0 + oy) * 8 + ox) * 128] = s;
        }
        #pragma unroll
        for (int j = 0; j < 10; j++) { r0[j] = r1[j]; r1[j] = r2[j]; }
    }
}

__global__ __launch_bounds__(256, 3) void k2_patch(const float* __restrict__ nw_g,
                                                   const float* __restrict__ nb_g,
                                                   float* __restrict__ out) {
    extern __shared__ float sm2[];
    float* sq  = sm2;
    float* sk  = sm2 + 8192;
    float* sA  = sm2 + 16384;
    float* sB  = sm2 + 16640;
    float* smu = sm2 + 16896;
    float* srs = sm2 + 16960;

    const int b = blockIdx.z, py = blockIdx.y, px = blockIdx.x;
    const int t = threadIdx.x;
    const int ch = t & 127, h = t >> 7;
    const int oy0 = 4 * h;
    const float* hid = g_hidden + (size_t)b * HW * CH;
    const int y0 = py * 8, x0 = px * 8;

    dwconv_half(hid, ch,       y0, x0, oy0, sq + ch);
    dwconv_half(hid, 128 + ch, y0, x0, oy0, sk + ch);
    __syncthreads();

    float acc[32];
    #pragma unroll
    for (int i = 0; i < 32; i++) acc[i] = 0.f;
    {
        const float* sqc = sq + ch;
        const float* skc = sk + ch;
        #pragma unroll
        for (int a = 0; a < 8; a++) {
            float qr[8];
            #pragma unroll
            for (int bb = 0; bb < 8; bb++) qr[bb] = sqc[(a * 8 + bb) * 128];
            #pragma unroll
            for (int i = 0; i < 4; i++) {
                const int u = (oy0 + i - a) & 7;
                float kr[8];
                #pragma unroll
                for (int v = 0; v < 8; v++) kr[v] = skc[(u * 8 + v) * 128];
                #pragma unroll
                for (int bb = 0; bb < 8; bb++)
                    #pragma unroll
                    for (int v = 0; v < 8; v++)
                        acc[(i << 3) + ((bb + v) & 7)] += qr[bb] * kr[v];
            }
        }
    }
    __syncthreads();

    #pragma unroll
    for (int i = 0; i < 32; i++) sq[(oy0 * 8 + i) * 128 + ch] = acc[i];
    __syncthreads();

    {
        const int p = t & 63, g4 = t >> 6;
        float s = 0.f, s2 = 0.f;
        #pragma unroll 8
        for (int i = 0; i < 32; i++) {
            int c = g4 * 32 + i;
            float v = sq[p * 128 + ((c + p) & 127)];
            s += v; s2 += v * v;
        }
        sA[g4 * 64 + p] = s; sB[g4 * 64 + p] = s2;
    }
    __syncthreads();
    if (t < 64) {
        float s  = sA[t] + sA[t + 64] + sA[t + 128] + sA[t + 192];
        float s2 = sB[t] + sB[t + 64] + sB[t + 128] + sB[t + 192];
        float mu = s * (1.f / 128.f);
        float var = s2 * (1.f / 128.f) - mu * mu;
        smu[t] = mu;
        srs[t] = rsqrtf(var + 1e-5f);
    }
    __syncthreads();

    {
        float w9[9];
        #pragma unroll
        for (int k = 0; k < 9; k++) w9[k] = g_wdw_t[k * 384 + 256 + ch];
        const float nw = nw_g[ch], nb = nb_g[ch];
        float r0[10], r1[10], r2[10];
        loadrow10(r0, hid, y0 + oy0 - 1, x0, 256 + ch);
        loadrow10(r1, hid, y0 + oy0,     x0, 256 + ch);
        #pragma unroll
        for (int oy = 0; oy < 4; oy++) {
            loadrow10(r2, hid, y0 + oy0 + oy + 1, x0, 256 + ch);
            #pragma unroll
            for (int ox = 0; ox < 8; ox++) {
                float v = r0[ox] * w9[0] + r0[ox + 1] * w9[1] + r0[ox + 2] * w9[2]
                        + r1[ox] * w9[3] + r1[ox + 1] * w9[4] + r1[ox + 2] * w9[5]
                        + r2[ox] * w9[6] + r2[ox + 1] * w9[7] + r2[ox + 2] * w9[8];
                int p = (oy0 + oy) * 8 + ox;
                float nrm = (sq[p * 128 + ch] - smu[p]) * srs[p] * nw + nb;
                sk[p * 128 + ch] = v * nrm;
            }
            #pragma unroll
            for (int j = 0; j < 10; j++) { r0[j] = r1[j]; r1[j] = r2[j]; }
        }
    }
    __syncthreads();

    {
        const int o = t & 63, ph = t >> 6, p0 = ph << 4;
        u64 pa[16];
        #pragma unroll
        for (int p = 0; p < 16; p++) pa[p] = 0ULL;
        #pragma unroll 2
        for (int c4 = 0; c4 < 32; c4++) {
            float2 w01 = __ldg(&g_wout_p[(2 * c4) * 64 + o]);
            float2 w23 = __ldg(&g_wout_p[(2 * c4 + 1) * 64 + o]);
            u64 wq01 = pack2(w01.x, w01.y);
            u64 wq23 = pack2(w23.x, w23.y);
            const float* gk = sk + 4 * c4;
            #pragma unroll
            for (int p = 0; p < 16; p++) {
                ulonglong2 g = *(const ulonglong2*)(gk + (p0 + p) * 128);
                ffma2(pa[p], g.x, wq01);
                ffma2(pa[p], g.y, wq23);
            }
        }
        #pragma unroll
        for (int p = 0; p < 16; p++) {
            float lo, hi; unpack2(lo, hi, pa[p]);
            sq[o * 66 + p0 + p] = lo + hi;
        }
    }
    __syncthreads();

    for (int i = t; i < 4096; i += 256) {
        int oo = i >> 6, p = i & 63;
        int y = y0 + (p >> 3), x = x0 + (p & 7);
        out[(((size_t)b * 64 + oo) * IMGW + y) * IMGW + x] = sq[oo * 66 + p];
    }
}

// ---------------------------------------------------------------------------
extern "C" void kernel_launch(void* const* d_in, const int* in_sizes, int n_in,
                              void* d_out, int out_size) {
    const float* x    = (const float*)d_in[0];
    const float* wh   = (const float*)d_in[1];
    const float* wdw  = (const float*)d_in[2];
    const float* nw   = (const float*)d_in[3];
    const float* nb   = (const float*)d_in[4];
    const float* wout = (const float*)d_in[5];
    float* out = (float*)d_out;

    cudaFuncSetAttribute(k1_conv1x1, cudaFuncAttributeMaxDynamicSharedMemorySize, 34816);
    cudaFuncSetAttribute(k2_patch,   cudaFuncAttributeMaxDynamicSharedMemorySize, 68096);

    k1_conv1x1<<<dim3(512, 3, 4), 256, 34816>>>(x, wh, wdw, wout);
    k2_patch<<<dim3(32, 32, 4), 256, 68096>>>(nw, nb, out);
}